// round 5
// baseline (speedup 1.0000x reference)
#include <cuda_runtime.h>

// ExtractTensorPatches: x (4,32,256,256) f32 -> out (4,961,32,16,16) f32
// out[b,l,c,i,j] = x[b,c,oh*8+i,ow*8+j] + EPS * patch_sum(b,c,oh,ow)
// l = oh*31 + ow.
//
// One CTA per (b,c,oh): loads 16x256 input row band into smem once,
// computes all 31 patch sums, streams out 31 patches of 256 floats.
// Output stores are write-through (__stwt): no dirty output lines in L2,
// so the 33.5 MB input stays L2-resident across graph-replay iterations.

#define CHAN   32
#define HW     256
#define WIN    16
#define STR    8
#define HO     31
#define WO     31
#define LPATCH (HO * WO)       // 961
#define TPAD   272             // 256 + 16 pad: rows i/i+1 hit disjoint bank halves

__device__ __forceinline__ float4 ld4g(const float* p) {
    return *reinterpret_cast<const float4*>(p);
}

__global__ __launch_bounds__(256)
void extract_patches_kernel(const float* __restrict__ x, float* __restrict__ out) {
    const float EPS = 1e-6f;

    __shared__ float tile[WIN][TPAD];     // 16 rows x 256 (+16 pad) floats
    __shared__ float part[64][5];         // per-(col4, row-group) partials (pad 5)
    __shared__ float colsum4[64];         // sum over 16 rows of each 4-col group
    __shared__ float psum[WO + 1];        // 31 patch sums

    int bx = blockIdx.x;
    int oh = bx % HO;
    int c  = (bx / HO) & (CHAN - 1);
    int b  = bx / (HO * CHAN);

    int tid  = threadIdx.x;
    int wid  = tid >> 5;
    int lane = tid & 31;

    const float* src = x + ((size_t)(b * CHAN + c) * HW + (size_t)(oh * STR)) * HW;

    // ---- Phase 1: load 16x256 band (1024 float4s; 4 per thread), accumulate
    // per-thread partial sum. Thread covers fixed col4 = tid&63, rows r0+{0,4,8,12}.
    int col4 = tid & 63;
    int r0   = tid >> 6;
    float acc = 0.f;
    #pragma unroll
    for (int k = 0; k < 4; k++) {
        int r = r0 + 4 * k;
        float4 v = ld4g(src + (size_t)r * HW + col4 * 4);
        acc += v.x + v.y + v.z + v.w;
        *reinterpret_cast<float4*>(&tile[r][col4 * 4]) = v;
    }
    part[col4][r0] = acc;
    __syncthreads();

    // ---- Phase 2: column-group sums over all 16 rows (threads 0..63)
    if (tid < 64) {
        colsum4[tid] = part[tid][0] + part[tid][1] + part[tid][2] + part[tid][3];
    }
    __syncthreads();

    // ---- Phase 3: patch sums (threads 0..30): window = 4 consecutive 4-col
    // groups starting at group 2*ow.
    if (tid < WO) {
        int g0 = 2 * tid;
        psum[tid] = colsum4[g0] + colsum4[g0 + 1] + colsum4[g0 + 2] + colsum4[g0 + 3];
    }
    __syncthreads();

    // ---- Phase 4: 62 tasks (31 patches x 2 half-patches of 512B each),
    // flat-distributed over 8 warps. Write-through stores.
    size_t out_base = (((size_t)b * LPATCH + (size_t)oh * WO) * CHAN + c) * (size_t)(WIN * WIN);
    #pragma unroll
    for (int t = wid; t < 62; t += 8) {
        int p = t >> 1;            // patch ow
        int h = t & 1;             // half of patch
        int q = lane + 32 * h;     // float4 index within patch, 0..63
        int i = q >> 2;            // patch row
        int s = q & 3;             // 4-float segment within row

        float4 v = *reinterpret_cast<const float4*>(&tile[i][p * STR + s * 4]);
        float e = EPS * psum[p];
        v.x += e; v.y += e; v.z += e; v.w += e;

        float* dst = out + out_base + (size_t)p * (CHAN * WIN * WIN) + q * 4;
        __stwt(reinterpret_cast<float4*>(dst), v);
    }
}

extern "C" void kernel_launch(void* const* d_in, const int* in_sizes, int n_in,
                              void* d_out, int out_size) {
    const float* x = (const float*)d_in[0];
    float* out = (float*)d_out;

    dim3 grid(4 * CHAN * HO);   // 3968 CTAs: one per (b, c, oh)
    dim3 block(256);
    extract_patches_kernel<<<grid, block>>>(x, out);
}

// round 6
// speedup vs baseline: 1.0850x; 1.0850x over previous
#include <cuda_runtime.h>

// ExtractTensorPatches: x (4,32,256,256) f32 -> out (4,961,32,16,16) f32
// out[b,l,c,i,j] = x[b,c,oh*8+i,ow*8+j] + EPS * patch_sum(b,c,oh,ow)
// l = oh*31 + ow.
//
// One CTA per (b,c,oh-PAIR): loads a 24x256 band (rows for oh0 and oh0+1,
// sharing the middle 8 rows) once, computes 62 patch sums, writes 62 patches.
// Cuts global-read requests 25% vs one-band-per-CTA.

#define CHAN   32
#define HW     256
#define WIN    16
#define STR    8
#define HO     31
#define WO     31
#define LPATCH (HO * WO)       // 961
#define NPAIR  16              // pairs (0,1)..(28,29),(30,-)
#define TPAD   272             // rows i/i+1 hit disjoint bank halves

__device__ __forceinline__ float4 ld4g(const float* p) {
    return *reinterpret_cast<const float4*>(p);
}

__global__ __launch_bounds__(256)
void extract_patches_kernel(const float* __restrict__ x, float* __restrict__ out) {
    const float EPS = 1e-6f;

    __shared__ float tile[24][TPAD];      // up to 24 rows x 256 floats
    __shared__ float part3[64][13];       // [col4][third*4 + r0], stride 13
    __shared__ float colsum[3][68];       // per-third 4-col sums
    __shared__ float psum[2][32];         // patch sums for oh0 / oh0+1

    int bx   = blockIdx.x;
    int pair = bx & (NPAIR - 1);
    int c    = (bx >> 4) & (CHAN - 1);
    int b    = bx >> 9;

    int oh0  = 2 * pair;
    bool full = (oh0 < HO - 1);           // pair 15 -> single band oh=30

    int tid  = threadIdx.x;
    int wid  = tid >> 5;
    int lane = tid & 31;

    const float* src = x + ((size_t)(b * CHAN + c) * HW + (size_t)(oh0 * STR)) * HW;

    // ---- Phase 1: load band (24 rows full / 16 rows edge), accumulate
    // per-thread partials per 8-row third. Thread: col4 = tid&63, rows r0+4k.
    int col4 = tid & 63;
    int r0   = tid >> 6;
    float a0 = 0.f, a1 = 0.f, a2 = 0.f;
    #pragma unroll
    for (int k = 0; k < 4; k++) {         // rows r0 .. r0+12 (thirds 0,0,1,1)
        int r = r0 + 4 * k;
        float4 v = ld4g(src + (size_t)r * HW + col4 * 4);
        float s = v.x + v.y + v.z + v.w;
        if (k < 2) a0 += s; else a1 += s;
        *reinterpret_cast<float4*>(&tile[r][col4 * 4]) = v;
    }
    if (full) {
        #pragma unroll
        for (int k = 4; k < 6; k++) {     // rows r0+16, r0+20 (third 2)
            int r = r0 + 4 * k;
            float4 v = ld4g(src + (size_t)r * HW + col4 * 4);
            a2 += v.x + v.y + v.z + v.w;
            *reinterpret_cast<float4*>(&tile[r][col4 * 4]) = v;
        }
    }
    part3[col4][0 + r0] = a0;
    part3[col4][4 + r0] = a1;
    part3[col4][8 + r0] = a2;
    __syncthreads();

    // ---- Phase 2: per-third column-group sums (192 threads: u = tid&63, t = tid>>6)
    if (tid < 192) {
        int u = tid & 63;
        int t = tid >> 6;
        colsum[t][u] = part3[u][4 * t] + part3[u][4 * t + 1]
                     + part3[u][4 * t + 2] + part3[u][4 * t + 3];
    }
    __syncthreads();

    // ---- Phase 3: patch sums. Thread tt<62: p = tt>>1, band j = tt&1.
    // psum[j][p] = sum over 4-col groups 2p..2p+3 of (third j + third j+1).
    if (tid < 62) {
        int p = tid >> 1;
        int j = tid & 1;
        int g0 = 2 * p;
        float s = 0.f;
        #pragma unroll
        for (int g = 0; g < 4; g++)
            s += colsum[j][g0 + g] + colsum[j + 1][g0 + g];
        psum[j][p] = s;
    }
    __syncthreads();

    // ---- Phase 4: tasks = (#bands)*62 half-patches of 512B, over 8 warps.
    int T = full ? 124 : 62;
    size_t out_row0 = ((size_t)b * LPATCH + (size_t)oh0 * WO);  // l of (oh0, ow=0)
    for (int t = wid; t < T; t += 8) {
        int ow, j, h;
        if (full) { ow = t >> 2; j = (t >> 1) & 1; h = t & 1; }
        else      { ow = t >> 1; j = 0;            h = t & 1; }

        int q = lane + 32 * h;       // float4 index within patch, 0..63
        int i = q >> 2;              // patch row
        int s = q & 3;               // 4-float segment

        float4 v = *reinterpret_cast<const float4*>(&tile[j * STR + i][ow * STR + s * 4]);
        float e = EPS * psum[j][ow];
        v.x += e; v.y += e; v.z += e; v.w += e;

        size_t l = out_row0 + (size_t)j * WO + ow;
        float* dst = out + ((l * CHAN + c) << 8) + q * 4;
        __stcs(reinterpret_cast<float4*>(dst), v);
    }
}

extern "C" void kernel_launch(void* const* d_in, const int* in_sizes, int n_in,
                              void* d_out, int out_size) {
    const float* x = (const float*)d_in[0];
    float* out = (float*)d_out;

    dim3 grid(4 * CHAN * NPAIR);   // 2048 CTAs: one per (b, c, oh-pair)
    dim3 block(256);
    extract_patches_kernel<<<grid, block>>>(x, out);
}